// round 3
// baseline (speedup 1.0000x reference)
#include <cuda_runtime.h>
#include <math.h>

#define NEXP 16
#define MAX_T 4096
#define NCHUNK 16

// Scratch (allocation-free per harness rules)
__device__ float g_probs[NEXP * MAX_T];   // [e][t] transposed for coalesced aux reduce
__device__ float g_s0[MAX_T];
__device__ float g_s1[MAX_T];
__device__ int   g_i0[MAX_T];
__device__ int   g_i1[MAX_T];

// ---------------------------------------------------------------------------
// Kernel 1: gating. One warp per token, float4-vectorized.
// Per h-iteration: 1x hs LDG.128 (streaming, .cs) + 16x gw LDG.128 (L1-cached,
// gw = 131KB fits in 228KB L1) -> MLP ~16, 4x fewer load instructions.
// ---------------------------------------------------------------------------
__global__ void gate_kernel(const float4* __restrict__ hs,
                            const float4* __restrict__ gw,
                            int T, int H4) {
    int warp = (blockIdx.x * blockDim.x + threadIdx.x) >> 5;
    int lane = threadIdx.x & 31;
    if (warp >= T) return;

    const float4* hrow = hs + (size_t)warp * H4;
    float acc[NEXP];
#pragma unroll
    for (int e = 0; e < NEXP; e++) acc[e] = 0.f;

    for (int h = lane; h < H4; h += 32) {
        float4 hv = __ldcs(&hrow[h]);
#pragma unroll
        for (int e = 0; e < NEXP; e++) {
            float4 w = __ldg(&gw[(size_t)e * H4 + h]);
            float t0 = fmaf(hv.x, w.x, hv.y * w.y);
            float t1 = fmaf(hv.z, w.z, hv.w * w.w);
            acc[e] += t0 + t1;
        }
    }

#pragma unroll
    for (int e = 0; e < NEXP; e++) {
#pragma unroll
        for (int off = 16; off; off >>= 1)
            acc[e] += __shfl_xor_sync(0xffffffffu, acc[e], off);
    }

    if (lane == 0) {
        float m = acc[0];
#pragma unroll
        for (int e = 1; e < NEXP; e++) m = fmaxf(m, acc[e]);
        float p[NEXP];
        float sum = 0.f;
#pragma unroll
        for (int e = 0; e < NEXP; e++) { p[e] = __expf(acc[e] - m); sum += p[e]; }
        float inv = 1.f / sum;
#pragma unroll
        for (int e = 0; e < NEXP; e++) {
            p[e] *= inv;
            g_probs[e * MAX_T + warp] = p[e];
        }
        // top-2 (lowest index wins ties, matching lax.top_k)
        float b0 = -1.f, b1 = -1.f;
        int   bi0 = 0,   bi1 = 0;
#pragma unroll
        for (int e = 0; e < NEXP; e++) {
            if (p[e] > b0)      { b1 = b0; bi1 = bi0; b0 = p[e]; bi0 = e; }
            else if (p[e] > b1) { b1 = p[e]; bi1 = e; }
        }
        float s = 1.f / (b0 + b1);
        g_s0[warp] = b0 * s;
        g_s1[warp] = b1 * s;
        g_i0[warp] = bi0;
        g_i1[warp] = bi1;
    }
}

// ---------------------------------------------------------------------------
// Kernel 2: bias = s0*eb[i0] + s1*eb[i1]. Block owns one V-chunk (CV floats),
// stages ALL 16 experts' chunk slices into smem once (16*CV*4 bytes), then
// loops over tokens reading from smem -> eb touched once from HBM total,
// leaving only the 262MB output write stream (pure DRAM-write bound).
// Aux loss is fused into block (0,0), hidden under the grid.
// ---------------------------------------------------------------------------
__global__ void bias_kernel(const float* __restrict__ eb,
                            float* __restrict__ out,
                            int T, int V, int CV, int has_aux) {
    extern __shared__ float sm[];
    const int tid = threadIdx.x;

    // Fused aux loss: only block (0,0), before smem is repurposed.
    if (has_aux && blockIdx.x == 0 && blockIdx.y == 0) {
        int e = tid >> 5, lane = tid & 31;
        float s = 0.f;
        if (e < NEXP)
            for (int t = lane; t < T; t += 32)
                s += g_probs[e * MAX_T + t];
#pragma unroll
        for (int off = 16; off; off >>= 1)
            s += __shfl_xor_sync(0xffffffffu, s, off);
        if (e < NEXP && lane == 0) sm[e] = s / (float)T;
        __syncthreads();
        if (tid == 0) {
            float a = 0.f;
#pragma unroll
            for (int i = 0; i < NEXP; i++)
                a += sm[i] * logf(sm[i]);
            out[(size_t)T * V] = a * (float)NEXP;
        }
        __syncthreads();
    }

    // Stage 16 expert chunk-slices into smem (float4 coalesced).
    const int c0 = blockIdx.x * CV;
    const int CV4 = CV >> 2;
    for (int i = tid; i < NEXP * CV4; i += blockDim.x) {
        int e = i / CV4;
        int v = i - e * CV4;
        ((float4*)sm)[i] =
            __ldg((const float4*)(eb + (size_t)e * V + c0) + v);
    }
    __syncthreads();

    // Grid-stride over tokens (gridDim.y strided -> perfect balance).
    for (int t = blockIdx.y; t < T; t += gridDim.y) {
        float s0 = g_s0[t];
        float s1 = g_s1[t];
        const float4* r0 = (const float4*)(sm + g_i0[t] * CV);
        const float4* r1 = (const float4*)(sm + g_i1[t] * CV);
        float4* o = (float4*)(out + (size_t)t * V + c0);
        for (int v = tid; v < CV4; v += blockDim.x) {
            float4 a = r0[v];
            float4 b = r1[v];
            float4 r;
            r.x = fmaf(s0, a.x, s1 * b.x);
            r.y = fmaf(s0, a.y, s1 * b.y);
            r.z = fmaf(s0, a.z, s1 * b.z);
            r.w = fmaf(s0, a.w, s1 * b.w);
            __stcs(&o[v], r);
        }
    }
}

extern "C" void kernel_launch(void* const* d_in, const int* in_sizes, int n_in,
                              void* d_out, int out_size) {
    const float* hs = (const float*)d_in[0];  // (T, H)
    const float* gw = (const float*)d_in[1];  // (E, H)
    const float* eb = (const float*)d_in[2];  // (E, V)
    float* out = (float*)d_out;

    int H = in_sizes[1] / NEXP;
    int T = in_sizes[0] / H;
    int V = in_sizes[2] / NEXP;
    int H4 = H >> 2;
    int CV = V / NCHUNK;          // 2000 for V=32000; CV % 4 == 0

    // 1. gating: one warp per token, float4
    {
        int threads = 256;
        int blocks = (T * 32 + threads - 1) / threads;
        gate_kernel<<<blocks, threads>>>((const float4*)hs, (const float4*)gw,
                                         T, H4);
    }

    // 2. bias (+fused aux): grid = 16 chunks x 37 token-stripes = 592 blocks
    //    = exactly 4 waves of 148 SMs. 128KB dynamic smem per block.
    {
        long long tv = (long long)T * (long long)V;
        int has_aux = ((long long)out_size > tv) ? 1 : 0;
        int smem_bytes = NEXP * CV * (int)sizeof(float);   // 128000
        cudaFuncSetAttribute(bias_kernel,
                             cudaFuncAttributeMaxDynamicSharedMemorySize,
                             smem_bytes);
        dim3 grid(NCHUNK, 37);
        bias_kernel<<<grid, 512, smem_bytes>>>(eb, out, T, V, CV, has_aux);
    }
}

// round 6
// speedup vs baseline: 1.9961x; 1.9961x over previous
#include <cuda_runtime.h>
#include <math.h>

#define NEXP 16
#define MAX_T 4096

// Scratch (allocation-free per harness rules)
__device__ float g_probs[NEXP * MAX_T];   // [e][t] for coalesced aux reduce
__device__ float g_s0[MAX_T];
__device__ float g_s1[MAX_T];
__device__ int   g_i0[MAX_T];
__device__ int   g_i1[MAX_T];

// ---------------------------------------------------------------------------
// Kernel 1: gating. One warp per 2 tokens, float4-vectorized.
// Per h-iteration: 2x hs LDG.128 + 16x gw LDG.128 (L1-resident, gw = 131KB)
// shared across both tokens -> halves gw L1 traffic vs 1 tok/warp.
// ---------------------------------------------------------------------------
__global__ void gate_kernel(const float4* __restrict__ hs,
                            const float4* __restrict__ gw,
                            int T, int H4) {
    int warp = (blockIdx.x * blockDim.x + threadIdx.x) >> 5;
    int lane = threadIdx.x & 31;
    int t0 = warp * 2;
    if (t0 >= T) return;
    int t1 = t0 + 1;
    bool has1 = (t1 < T);

    const float4* hrow0 = hs + (size_t)t0 * H4;
    const float4* hrow1 = hs + (size_t)(has1 ? t1 : t0) * H4;

    float acc0[NEXP], acc1[NEXP];
#pragma unroll
    for (int e = 0; e < NEXP; e++) { acc0[e] = 0.f; acc1[e] = 0.f; }

    for (int h = lane; h < H4; h += 32) {
        float4 hv0 = hrow0[h];
        float4 hv1 = hrow1[h];
#pragma unroll
        for (int e = 0; e < NEXP; e++) {
            float4 w = __ldg(&gw[(size_t)e * H4 + h]);
            acc0[e] += fmaf(hv0.x, w.x, hv0.y * w.y)
                     + fmaf(hv0.z, w.z, hv0.w * w.w);
            acc1[e] += fmaf(hv1.x, w.x, hv1.y * w.y)
                     + fmaf(hv1.z, w.z, hv1.w * w.w);
        }
    }

#pragma unroll
    for (int e = 0; e < NEXP; e++) {
#pragma unroll
        for (int off = 16; off; off >>= 1) {
            acc0[e] += __shfl_xor_sync(0xffffffffu, acc0[e], off);
            acc1[e] += __shfl_xor_sync(0xffffffffu, acc1[e], off);
        }
    }

    if (lane == 0) {
#pragma unroll
        for (int which = 0; which < 2; which++) {
            if (which == 1 && !has1) break;
            int tk = t0 + which;
            float* acc = which ? acc1 : acc0;

            float m = acc[0];
#pragma unroll
            for (int e = 1; e < NEXP; e++) m = fmaxf(m, acc[e]);
            float p[NEXP];
            float sum = 0.f;
#pragma unroll
            for (int e = 0; e < NEXP; e++) { p[e] = __expf(acc[e] - m); sum += p[e]; }
            float inv = 1.f / sum;
#pragma unroll
            for (int e = 0; e < NEXP; e++) {
                p[e] *= inv;
                g_probs[e * MAX_T + tk] = p[e];
            }
            // top-2 (lowest index wins ties, matching lax.top_k)
            float b0 = -1.f, b1 = -1.f;
            int   bi0 = 0,   bi1 = 0;
#pragma unroll
            for (int e = 0; e < NEXP; e++) {
                if (p[e] > b0)      { b1 = b0; bi1 = bi0; b0 = p[e]; bi0 = e; }
                else if (p[e] > b1) { b1 = p[e]; bi1 = e; }
            }
            float s = 1.f / (b0 + b1);
            g_s0[tk] = b0 * s;
            g_s1[tk] = b1 * s;
            g_i0[tk] = bi0;
            g_i1[tk] = bi1;
        }
    }
}

// ---------------------------------------------------------------------------
// Kernel 2: bias = s0*eb[i0] + s1*eb[i1]. One thread per 2 float4s, no smem,
// full occupancy. eb (2MB) is L2-resident; output (262MB) is the pure DRAM
// write bottleneck -> __stcs streaming stores. Aux fused into block (0,0).
// NOTE: block = 256 threads = 8 warps -> each warp reduces TWO experts.
// ---------------------------------------------------------------------------
__global__ void bias_kernel(const float* __restrict__ eb,
                            float* __restrict__ out,
                            int T, int V, int has_aux) {
    // Fused aux loss (block (0,0) only, tiny static smem)
    if (has_aux && blockIdx.x == 0 && blockIdx.y == 0) {
        __shared__ float su[NEXP];
        int w = threadIdx.x >> 5, lane = threadIdx.x & 31;   // w in [0,8)
#pragma unroll
        for (int half = 0; half < 2; half++) {
            int e = w + half * 8;                            // covers 0..15
            float s = 0.f;
            for (int t = lane; t < T; t += 32)
                s += g_probs[e * MAX_T + t];
#pragma unroll
            for (int off = 16; off; off >>= 1)
                s += __shfl_xor_sync(0xffffffffu, s, off);
            if (lane == 0) su[e] = s / (float)T;
        }
        __syncthreads();
        if (threadIdx.x == 0) {
            float a = 0.f;
#pragma unroll
            for (int i = 0; i < NEXP; i++)
                a += su[i] * logf(su[i]);
            out[(size_t)T * V] = a * (float)NEXP;
        }
    }

    const int t = blockIdx.y;
    const int V4 = V >> 2;
    const float s0 = g_s0[t];
    const float s1 = g_s1[t];
    const float4* e0 = (const float4*)(eb + (size_t)g_i0[t] * V);
    const float4* e1 = (const float4*)(eb + (size_t)g_i1[t] * V);
    float4* o = (float4*)(out + (size_t)t * V);

    // 2 independent float4s per thread (4 loads in flight)
    int base = (blockIdx.x * blockDim.x) * 2 + threadIdx.x;
    int vA = base;
    int vB = base + blockDim.x;

    if (vA < V4) {
        float4 a0 = __ldg(&e0[vA]);
        float4 b0 = __ldg(&e1[vA]);
        bool hasB = (vB < V4);
        float4 a1, b1;
        if (hasB) { a1 = __ldg(&e0[vB]); b1 = __ldg(&e1[vB]); }

        float4 r0;
        r0.x = fmaf(s0, a0.x, s1 * b0.x);
        r0.y = fmaf(s0, a0.y, s1 * b0.y);
        r0.z = fmaf(s0, a0.z, s1 * b0.z);
        r0.w = fmaf(s0, a0.w, s1 * b0.w);
        __stcs(&o[vA], r0);

        if (hasB) {
            float4 r1;
            r1.x = fmaf(s0, a1.x, s1 * b1.x);
            r1.y = fmaf(s0, a1.y, s1 * b1.y);
            r1.z = fmaf(s0, a1.z, s1 * b1.z);
            r1.w = fmaf(s0, a1.w, s1 * b1.w);
            __stcs(&o[vB], r1);
        }
    }
}

extern "C" void kernel_launch(void* const* d_in, const int* in_sizes, int n_in,
                              void* d_out, int out_size) {
    const float* hs = (const float*)d_in[0];  // (T, H)
    const float* gw = (const float*)d_in[1];  // (E, H)
    const float* eb = (const float*)d_in[2];  // (E, V)
    float* out = (float*)d_out;

    int H = in_sizes[1] / NEXP;
    int T = in_sizes[0] / H;
    int V = in_sizes[2] / NEXP;
    int H4 = H >> 2;

    // 1. gating: one warp per 2 tokens
    {
        int nwarps = (T + 1) / 2;
        int threads = 256;
        int blocks = (nwarps * 32 + threads - 1) / threads;
        gate_kernel<<<blocks, threads>>>((const float4*)hs, (const float4*)gw,
                                         T, H4);
    }

    // 2. bias (+fused aux): grid.x covers V4 with 2 float4/thread
    {
        long long tv = (long long)T * (long long)V;
        int has_aux = ((long long)out_size > tv) ? 1 : 0;
        int V4 = V >> 2;
        int threads = 256;
        int bx = (V4 + threads * 2 - 1) / (threads * 2);
        dim3 grid(bx, T);
        bias_kernel<<<grid, threads>>>(eb, out, T, V, has_aux);
    }
}